// round 10
// baseline (speedup 1.0000x reference)
#include <cuda_runtime.h>

// MaxPool2d 3x3 stride 2 VALID, NCHW fp32.
// X: (32, 64, 224, 224) -> Y: (32, 64, 111, 111)

#define IH 224
#define IW 224
#define OH 111
#define OW 111
#define ORT 8              // output rows per block tile
#define IRT (2 * ORT + 1)  // 17 input rows per tile
#define NTHREADS 256

__global__ __launch_bounds__(NTHREADS)
void maxpool_kernel(const float* __restrict__ x, float* __restrict__ y) {
    const int bc   = blockIdx.y;           // which (b, c) image
    const int tile = blockIdx.x;           // which row tile
    const int r0   = tile * ORT;           // first output row of this tile
    const int orows = min(ORT, OH - r0);   // output rows this tile actually produces
    const int need  = 2 * orows + 1;       // input rows required (max index 2*110+2=222 < 224)
    const int ir0   = 2 * r0;

    const float* __restrict__ xp = x + (size_t)bc * IH * IW;
    float* __restrict__ yp       = y + (size_t)bc * OH * OW;

    __shared__ float raw[IRT][IW];      // raw input rows
    __shared__ float hm[IRT][OW + 1];   // horizontal 3-max per row (pad to 112)

    const int tid = threadIdx.x;

    // ---- Phase 1: coalesced float4 load of `need` contiguous input rows ----
    // Row start xp + ir0*IW is 16B-aligned (IW*4 = 896 bytes, image base 256B-aligned).
    {
        const float4* __restrict__ src = (const float4*)(xp + (size_t)ir0 * IW);
        float4* __restrict__ dst = (float4*)&raw[0][0];
        const int n4 = need * (IW / 4);  // up to 17*56 = 952 float4
        #pragma unroll 4
        for (int i = tid; i < n4; i += NTHREADS) {
            dst[i] = src[i];
        }
    }
    __syncthreads();

    // ---- Phase 2: horizontal 3-max (separable pooling) ----
    {
        const int n = need * OW;  // up to 17*111 = 1887
        for (int i = tid; i < n; i += NTHREADS) {
            const int rr = i / OW;
            const int q  = i - rr * OW;
            const int c  = 2 * q;
            hm[rr][q] = fmaxf(fmaxf(raw[rr][c], raw[rr][c + 1]), raw[rr][c + 2]);
        }
    }
    __syncthreads();

    // ---- Phase 3: vertical 3-max + coalesced store ----
    {
        const int n = orows * OW;  // up to 8*111 = 888
        for (int i = tid; i < n; i += NTHREADS) {
            const int rr = i / OW;
            const int q  = i - rr * OW;
            const int r2 = 2 * rr;
            float v = fmaxf(fmaxf(hm[r2][q], hm[r2 + 1][q]), hm[r2 + 2][q]);
            yp[(size_t)(r0 + rr) * OW + q] = v;
        }
    }
}

extern "C" void kernel_launch(void* const* d_in, const int* in_sizes, int n_in,
                              void* d_out, int out_size) {
    const float* x = (const float*)d_in[0];
    float* y = (float*)d_out;

    const int nbc = in_sizes[0] / (IH * IW);          // 32*64 = 2048
    const int ntiles = (OH + ORT - 1) / ORT;          // 14

    dim3 grid(ntiles, nbc);
    maxpool_kernel<<<grid, NTHREADS>>>(x, y);
}

// round 14
// speedup vs baseline: 1.5314x; 1.5314x over previous
#include <cuda_runtime.h>

// MaxPool2d 3x3 stride 2 VALID, NCHW fp32.
// X: (32, 64, 224, 224) -> Y: (32, 64, 111, 111)
//
// Direct-LDG register kernel (no smem, no barriers):
//   thread (t, yrow) -> outputs y[r][2t], y[r][2t+1]
//   loads x[2r..2r+2][4t..4t+4] as 3x(float4 + scalar), vertical max in regs,
//   then the two stride-2 horizontal 3-max windows.

#define IH 224
#define IW 224
#define OH 111
#define OW 111
#define TPR 56     // threads per output row: 56 * 2 outputs = 112 >= 111
#define RPB 8      // output rows per block
#define NTHREADS (TPR * RPB)  // 448

__global__ __launch_bounds__(NTHREADS)
void maxpool_kernel(const float* __restrict__ x, float* __restrict__ y) {
    const int bc = blockIdx.y;                          // (b, c) image
    const int r  = blockIdx.x * RPB + threadIdx.y;      // output row
    const int t  = threadIdx.x;                         // 0..55
    if (r >= OH) return;

    const float* __restrict__ xp =
        x + (size_t)bc * (IH * IW) + (size_t)(2 * r) * IW + 4 * t;

    // Three input rows, columns 4t..4t+3 (vectorized) — fully coalesced.
    const float4 a = *(const float4*)(xp);
    const float4 b = *(const float4*)(xp + IW);
    const float4 c = *(const float4*)(xp + 2 * IW);

    // Column 4t+4 (neighbor's first element) — L1 hit. OOB only for t==55,
    // where the second output is masked anyway.
    float e = __int_as_float(0xff800000);  // -inf
    if (t < TPR - 1) {
        const float ea = xp[4];
        const float eb = xp[IW + 4];
        const float ec = xp[2 * IW + 4];
        e = fmaxf(fmaxf(ea, eb), ec);
    }

    // Vertical 3-max per column.
    const float v0 = fmaxf(fmaxf(a.x, b.x), c.x);
    const float v1 = fmaxf(fmaxf(a.y, b.y), c.y);
    const float v2 = fmaxf(fmaxf(a.z, b.z), c.z);
    const float v3 = fmaxf(fmaxf(a.w, b.w), c.w);

    // Horizontal 3-max, stride-2 windows.
    const float o0 = fmaxf(fmaxf(v0, v1), v2);   // q = 2t   (cols 4t..4t+2)
    const float o1 = fmaxf(fmaxf(v2, v3), e);    // q = 2t+1 (cols 4t+2..4t+4)

    float* __restrict__ yp = y + (size_t)bc * (OH * OW) + (size_t)r * OW + 2 * t;
    yp[0] = o0;
    if (t < TPR - 1) yp[1] = o1;                 // q=111 does not exist
}

extern "C" void kernel_launch(void* const* d_in, const int* in_sizes, int n_in,
                              void* d_out, int out_size) {
    const float* x = (const float*)d_in[0];
    float* y = (float*)d_out;

    const int nbc = in_sizes[0] / (IH * IW);            // 32*64 = 2048
    const int ntiles = (OH + RPB - 1) / RPB;            // 14

    dim3 grid(ntiles, nbc);
    dim3 block(TPR, RPB);
    maxpool_kernel<<<grid, block>>>(x, y);
}